// round 2
// baseline (speedup 1.0000x reference)
#include <cuda_runtime.h>

// ---------------- problem constants ----------------
#define BSZ   4
#define NN    512
#define EMBD  64
#define INF   256          // IN_DIM
#define H1    128          // fc1 out (2*HD)
#define HE    64           // e1 out
#define NPAIR (NN*(NN-1))                 // 261632
#define PRED_OFF (BSZ*NN*NN)              // 1048576
#define EMB_OFF  (PRED_OFF + BSZ*NPAIR*2) // 3141632

// ---------------- device scratch (no allocs allowed) ----------------
__device__ float g_emb [BSZ*NN*EMBD];     // emb row-major   [b][n][k]
__device__ float g_embT[BSZ*EMBD*NN];     // emb transposed  [b][k][n]
__device__ float g_A   [BSZ*NN*HE];       // emb @ W1top     [b][n][h]

typedef unsigned long long ull;

// ---------------- helpers: packed f32x2 FMA ----------------
__device__ __forceinline__ ull pack2(float a) {
    ull r;
    asm("mov.b64 %0, {%1, %1};" : "=l"(r) : "f"(a));
    return r;
}
__device__ __forceinline__ void fma2(ull& d, ull a, ull b) {
    asm("fma.rn.f32x2 %0, %1, %2, %0;" : "+l"(d) : "l"(a), "l"(b));
}
__device__ __forceinline__ void unpack2(ull v, float& lo, float& hi) {
    asm("mov.b64 {%0, %1}, %2;" : "=f"(lo), "=f"(hi) : "l"(v));
}

// =====================================================================
// Stage 1: node MLP.  h = leaky(x@fc1+b1); emb = leaky(h@fc2+b2);
//          A = emb @ e1_w[:64,:].  Writes emb (out + scratch), embT, A.
// Grid: 128 blocks x 256 threads, 16 nodes per block.  (unchanged)
// =====================================================================
__global__ __launch_bounds__(256)
void stage1(const float* __restrict__ nf,
            const float* __restrict__ fc1w, const float* __restrict__ fc1b,
            const float* __restrict__ fc2w, const float* __restrict__ fc2b,
            const float* __restrict__ e1w,
            float* __restrict__ out)
{
    extern __shared__ float sm[];
    float* Xs = sm;             // 16*256 = 4096 floats
    float* Ws = Xs + 4096;      // up to 8192 floats (weight tile)
    float* Hs = Ws + 8192;      // 16*132 = 2112 floats (padded)
    float* Es = Hs + 2112;      // 16*64  = 1024 floats

    const int t  = threadIdx.x;
    const int nb = blockIdx.x * 16;          // first node of this block
    const int node = t >> 4;                 // 0..15
    const int sub  = t & 15;                 // 0..15

    // load X tile (flat copy, coalesced)
    #pragma unroll
    for (int r = 0; r < 16; r++)
        Xs[t + r*256] = nf[nb*INF + t + r*256];

    // ---- phase A: h = leaky(x @ fc1 + b1), per thread 8 h-outputs ----
    {
        const int hb = sub * 8;
        float acc[8];
        #pragma unroll
        for (int h = 0; h < 8; h++) acc[h] = 0.f;

        for (int kt = 0; kt < 4; kt++) {
            __syncthreads();
            #pragma unroll
            for (int r = 0; r < 32; r++)
                Ws[t + r*256] = fc1w[kt*64*H1 + t + r*256];
            __syncthreads();
            #pragma unroll
            for (int k = 0; k < 64; k++) {
                float x = Xs[node*INF + kt*64 + k];
                float4 w0 = *reinterpret_cast<const float4*>(&Ws[k*H1 + hb]);
                float4 w1 = *reinterpret_cast<const float4*>(&Ws[k*H1 + hb + 4]);
                acc[0] += x*w0.x; acc[1] += x*w0.y; acc[2] += x*w0.z; acc[3] += x*w0.w;
                acc[4] += x*w1.x; acc[5] += x*w1.y; acc[6] += x*w1.z; acc[7] += x*w1.w;
            }
        }
        #pragma unroll
        for (int h = 0; h < 8; h++) {
            float v = acc[h] + fc1b[hb + h];
            v = v > 0.f ? v : 0.01f * v;
            Hs[node*132 + hb + h] = v;
        }
    }

    // ---- phase B: emb = leaky(h @ fc2 + b2), per thread 4 outputs ----
    __syncthreads();
    #pragma unroll
    for (int r = 0; r < 32; r++)       // fc2w: 128*64 = 8192 floats
        Ws[t + r*256] = fc2w[t + r*256];
    __syncthreads();
    {
        const int db = sub * 4;
        float a0 = 0.f, a1 = 0.f, a2 = 0.f, a3 = 0.f;
        #pragma unroll
        for (int k = 0; k < H1; k++) {
            float hv = Hs[node*132 + k];
            float4 w = *reinterpret_cast<const float4*>(&Ws[k*EMBD + db]);
            a0 += hv*w.x; a1 += hv*w.y; a2 += hv*w.z; a3 += hv*w.w;
        }
        float v0 = a0 + fc2b[db+0]; v0 = v0 > 0.f ? v0 : 0.01f*v0;
        float v1 = a1 + fc2b[db+1]; v1 = v1 > 0.f ? v1 : 0.01f*v1;
        float v2 = a2 + fc2b[db+2]; v2 = v2 > 0.f ? v2 : 0.01f*v2;
        float v3 = a3 + fc2b[db+3]; v3 = v3 > 0.f ? v3 : 0.01f*v3;

        Es[node*EMBD + db + 0] = v0;
        Es[node*EMBD + db + 1] = v1;
        Es[node*EMBD + db + 2] = v2;
        Es[node*EMBD + db + 3] = v3;

        const int g = nb + node;
        float4 v4 = make_float4(v0, v1, v2, v3);
        *reinterpret_cast<float4*>(&g_emb[g*EMBD + db]) = v4;
        *reinterpret_cast<float4*>(&out[EMB_OFF + g*EMBD + db]) = v4;

        const int b = g >> 9;
        const int n = g & 511;
        g_embT[(b*EMBD + db + 0)*NN + n] = v0;
        g_embT[(b*EMBD + db + 1)*NN + n] = v1;
        g_embT[(b*EMBD + db + 2)*NN + n] = v2;
        g_embT[(b*EMBD + db + 3)*NN + n] = v3;
    }

    // ---- phase C: A = emb @ e1_w[:64,:], per thread 4 outputs ----
    __syncthreads();
    #pragma unroll
    for (int r = 0; r < 16; r++)       // e1w top half: 64*64 = 4096 floats
        Ws[t + r*256] = e1w[t + r*256];
    __syncthreads();
    {
        const int hb = sub * 4;
        float a0 = 0.f, a1 = 0.f, a2 = 0.f, a3 = 0.f;
        #pragma unroll
        for (int k = 0; k < EMBD; k++) {
            float ev = Es[node*EMBD + k];
            float4 w = *reinterpret_cast<const float4*>(&Ws[k*HE + hb]);
            a0 += ev*w.x; a1 += ev*w.y; a2 += ev*w.z; a3 += ev*w.w;
        }
        const int g = nb + node;
        *reinterpret_cast<float4*>(&g_A[g*HE + hb]) = make_float4(a0, a1, a2, a3);
    }
}

// =====================================================================
// Stage 2: edge MLP over all pairs.
// Block: 2 source nodes i, 256-wide j tiles (2 chunks), per-thread 8j x 8h.
// U_i = emb_i (.) W2 - W1 ; pre[j,h] = c_i[h] + emb_j @ U_i ; relu ;
// d = eh . wdiff + bdiff ; p1 = sigmoid(d).
// Grid: 1024 blocks x 256 threads, 2 CTAs/SM.
// =====================================================================
#define ETP 264   // Et pitch (256 + 8 pad)

__global__ __launch_bounds__(256, 2)
void stage2(const float* __restrict__ e1w, const float* __restrict__ e1b,
            const float* __restrict__ e2w, const float* __restrict__ e2b,
            float* __restrict__ out)
{
    extern __shared__ float sm[];
    float* U    = sm;               // 2*64*64 = 8192
    float* Et   = U + 8192;         // 64*264  = 16896
    float* red  = Et + 16896;       // 8*256   = 2048
    float* cc   = red + 2048;       // 2*64
    float* wd   = cc + 128;         // 64
    float* embi = wd + 64;          // 2*64
    float* bd   = embi + 128;       // 4 (pad)
    // total = 27464 floats = 109856 B

    const int t   = threadIdx.x;
    const int bid = blockIdx.x;
    const int b   = bid >> 8;            // batch
    const int i0  = (bid & 255) * 2;     // first source node

    if (t < 128) {
        int ii = t >> 6, h = t & 63;
        embi[t] = g_emb[(b*NN + i0 + ii)*EMBD + h];
        cc[t]   = g_A  [(b*NN + i0 + ii)*HE  + h] + e1b[h];
    } else if (t < 192) {
        int h = t - 128;
        wd[h] = e2w[h*2 + 1] - e2w[h*2 + 0];
    } else if (t == 192) {
        *bd = e2b[1] - e2b[0];
    }
    __syncthreads();

    // build U_i[k][h] = emb_i[k]*W2[k][h] - W1[k][h]
    #pragma unroll
    for (int ii = 0; ii < 2; ii++) {
        #pragma unroll
        for (int r = 0; r < 4; r++) {
            int idx = (t + r*256) * 4;     // 0..4095, step 4
            int k   = idx >> 6;
            int h4  = idx & 63;
            float e = embi[ii*64 + k];
            float4 w2 = *reinterpret_cast<const float4*>(&e1w[(64 + k)*HE + h4]);
            float4 w1 = *reinterpret_cast<const float4*>(&e1w[k*HE + h4]);
            float4 u;
            u.x = e*w2.x - w1.x; u.y = e*w2.y - w1.y;
            u.z = e*w2.z - w1.z; u.w = e*w2.w - w1.w;
            *reinterpret_cast<float4*>(&U[ii*4096 + k*64 + h4]) = u;
        }
    }
    __syncthreads();

    const int lane = t & 31;
    const int w    = t >> 5;     // h-group (warp) 0..7
    const int hb   = w * 8;
    const int l4   = lane * 4;

    float wdr[8];
    #pragma unroll
    for (int h = 0; h < 8; h++) wdr[h] = wd[hb + h];
    const float bdr = *bd;

    for (int chunk = 0; chunk < 2; chunk++) {
        const int jb = chunk * 256;

        // load E^T tile [64 k][256 j] from global (coalesced, conflict-free)
        #pragma unroll
        for (int r = 0; r < 16; r++) {
            int lin = t + r*256;            // 0..4095 float4 units
            int k   = lin >> 6;             // 64 float4 per row
            int j4  = (lin & 63) * 4;
            float4 v = *reinterpret_cast<const float4*>(
                &g_embT[(b*EMBD + k)*NN + jb + j4]);
            *reinterpret_cast<float4*>(&Et[k*ETP + j4]) = v;
        }
        __syncthreads();

        for (int ii = 0; ii < 2; ii++) {
            // acc[g][hp]: g = 0..3 -> j = l4+g ; g = 4..7 -> j = 128+l4+(g-4)
            ull acc[8][4];
            #pragma unroll
            for (int a = 0; a < 8; a++)
                #pragma unroll
                for (int c = 0; c < 4; c++) acc[a][c] = 0ull;

            const float* Ui = &U[ii*4096];

            #pragma unroll 4
            for (int k = 0; k < 64; k++) {
                float4 eA = *reinterpret_cast<const float4*>(&Et[k*ETP + l4]);
                float4 eB = *reinterpret_cast<const float4*>(&Et[k*ETP + 128 + l4]);
                const ull* up = reinterpret_cast<const ull*>(&Ui[k*64 + hb]);
                ull u0 = up[0], u1 = up[1], u2 = up[2], u3 = up[3];
                ull e;
                e = pack2(eA.x);
                fma2(acc[0][0], e, u0); fma2(acc[0][1], e, u1);
                fma2(acc[0][2], e, u2); fma2(acc[0][3], e, u3);
                e = pack2(eA.y);
                fma2(acc[1][0], e, u0); fma2(acc[1][1], e, u1);
                fma2(acc[1][2], e, u2); fma2(acc[1][3], e, u3);
                e = pack2(eA.z);
                fma2(acc[2][0], e, u0); fma2(acc[2][1], e, u1);
                fma2(acc[2][2], e, u2); fma2(acc[2][3], e, u3);
                e = pack2(eA.w);
                fma2(acc[3][0], e, u0); fma2(acc[3][1], e, u1);
                fma2(acc[3][2], e, u2); fma2(acc[3][3], e, u3);
                e = pack2(eB.x);
                fma2(acc[4][0], e, u0); fma2(acc[4][1], e, u1);
                fma2(acc[4][2], e, u2); fma2(acc[4][3], e, u3);
                e = pack2(eB.y);
                fma2(acc[5][0], e, u0); fma2(acc[5][1], e, u1);
                fma2(acc[5][2], e, u2); fma2(acc[5][3], e, u3);
                e = pack2(eB.z);
                fma2(acc[6][0], e, u0); fma2(acc[6][1], e, u1);
                fma2(acc[6][2], e, u2); fma2(acc[6][3], e, u3);
                e = pack2(eB.w);
                fma2(acc[7][0], e, u0); fma2(acc[7][1], e, u1);
                fma2(acc[7][2], e, u2); fma2(acc[7][3], e, u3);
            }

            // epilogue: relu + dot with wdiff (partial over this warp's 8 h)
            float pr[8];
            #pragma unroll
            for (int g = 0; g < 8; g++) {
                float p = 0.f;
                #pragma unroll
                for (int hp = 0; hp < 4; hp++) {
                    float lo, hi;
                    unpack2(acc[g][hp], lo, hi);
                    float pre0 = lo + cc[ii*64 + hb + hp*2 + 0];
                    float pre1 = hi + cc[ii*64 + hb + hp*2 + 1];
                    pre0 = fmaxf(pre0, 0.f);
                    pre1 = fmaxf(pre1, 0.f);
                    p += pre0 * wdr[hp*2 + 0] + pre1 * wdr[hp*2 + 1];
                }
                pr[g] = p;
            }
            *reinterpret_cast<float4*>(&red[w*256 + l4]) =
                make_float4(pr[0], pr[1], pr[2], pr[3]);
            *reinterpret_cast<float4*>(&red[w*256 + 128 + l4]) =
                make_float4(pr[4], pr[5], pr[6], pr[7]);
            __syncthreads();

            // final reduce over 8 warps: thread t handles j-slot t
            {
                float d = bdr;
                #pragma unroll
                for (int ww = 0; ww < 8; ww++) d += red[ww*256 + t];
                // numerically stable 2-class softmax
                float ad  = fabsf(d);
                float ex  = __expf(-ad);
                float inv = 1.f / (1.f + ex);
                float pbig = inv, psml = ex * inv;
                float p1 = d >= 0.f ? pbig : psml;
                float p0 = d >= 0.f ? psml : pbig;

                const int ig = i0 + ii;
                const int j  = jb + t;
                out[b*NN*NN + ig*NN + j] = p1;            // adjacency
                if (j != ig) {
                    int kidx = ig*(NN-1) + (j < ig ? j : j - 1);
                    *reinterpret_cast<float2*>(
                        &out[PRED_OFF + (b*NPAIR + kidx)*2]) = make_float2(p0, p1);
                }
            }
            __syncthreads();
        }
    }
}

// =====================================================================
extern "C" void kernel_launch(void* const* d_in, const int* in_sizes, int n_in,
                              void* d_out, int out_size)
{
    (void)in_sizes; (void)n_in; (void)out_size;
    const float* nf   = (const float*)d_in[0];
    const float* fc1w = (const float*)d_in[1];
    const float* fc1b = (const float*)d_in[2];
    const float* fc2w = (const float*)d_in[3];
    const float* fc2b = (const float*)d_in[4];
    const float* e1w  = (const float*)d_in[5];
    const float* e1b  = (const float*)d_in[6];
    const float* e2w  = (const float*)d_in[7];
    const float* e2b  = (const float*)d_in[8];
    float* out = (float*)d_out;

    const int smem1 = 15424 * 4;   // 61696 B
    const int smem2 = 27464 * 4;   // 109856 B
    cudaFuncSetAttribute(stage1, cudaFuncAttributeMaxDynamicSharedMemorySize, smem1);
    cudaFuncSetAttribute(stage2, cudaFuncAttributeMaxDynamicSharedMemorySize, smem2);

    stage1<<<128, 256, smem1>>>(nf, fc1w, fc1b, fc2w, fc2b, e1w, out);
    stage2<<<1024, 256, smem2>>>(e1w, e1b, e2w, e2b, out);
}

// round 4
// speedup vs baseline: 2.4912x; 2.4912x over previous
#include <cuda_runtime.h>

// ---------------- problem constants ----------------
#define BSZ   4
#define NN    512
#define EMBD  64
#define INF   256          // IN_DIM
#define H1    128          // fc1 out (2*HD)
#define HE    64           // e1 out
#define NPAIR (NN*(NN-1))                 // 261632
#define PRED_OFF (BSZ*NN*NN)              // 1048576
#define EMB_OFF  (PRED_OFF + BSZ*NPAIR*2) // 3141632

// ---------------- device scratch (no allocs allowed) ----------------
__device__ float g_emb[BSZ*NN*EMBD];     // emb row-major [b][n][k]
__device__ float g_A  [BSZ*NN*HE];       // emb @ W1top   [b][n][h]

typedef unsigned int u32;

// =====================================================================
// Stage 1: node MLP (unchanged).
// =====================================================================
__global__ __launch_bounds__(256)
void stage1(const float* __restrict__ nf,
            const float* __restrict__ fc1w, const float* __restrict__ fc1b,
            const float* __restrict__ fc2w, const float* __restrict__ fc2b,
            const float* __restrict__ e1w,
            float* __restrict__ out)
{
    extern __shared__ float sm[];
    float* Xs = sm;             // 16*256 = 4096 floats
    float* Ws = Xs + 4096;      // up to 8192 floats
    float* Hs = Ws + 8192;      // 16*132 = 2112
    float* Es = Hs + 2112;      // 16*64  = 1024

    const int t  = threadIdx.x;
    const int nb = blockIdx.x * 16;
    const int node = t >> 4;
    const int sub  = t & 15;

    #pragma unroll
    for (int r = 0; r < 16; r++)
        Xs[t + r*256] = nf[nb*INF + t + r*256];

    {   // phase A: h = leaky(x@fc1+b1)
        const int hb = sub * 8;
        float acc[8];
        #pragma unroll
        for (int h = 0; h < 8; h++) acc[h] = 0.f;
        for (int kt = 0; kt < 4; kt++) {
            __syncthreads();
            #pragma unroll
            for (int r = 0; r < 32; r++)
                Ws[t + r*256] = fc1w[kt*64*H1 + t + r*256];
            __syncthreads();
            #pragma unroll
            for (int k = 0; k < 64; k++) {
                float x = Xs[node*INF + kt*64 + k];
                float4 w0 = *reinterpret_cast<const float4*>(&Ws[k*H1 + hb]);
                float4 w1 = *reinterpret_cast<const float4*>(&Ws[k*H1 + hb + 4]);
                acc[0] += x*w0.x; acc[1] += x*w0.y; acc[2] += x*w0.z; acc[3] += x*w0.w;
                acc[4] += x*w1.x; acc[5] += x*w1.y; acc[6] += x*w1.z; acc[7] += x*w1.w;
            }
        }
        #pragma unroll
        for (int h = 0; h < 8; h++) {
            float v = acc[h] + fc1b[hb + h];
            v = v > 0.f ? v : 0.01f * v;
            Hs[node*132 + hb + h] = v;
        }
    }

    __syncthreads();
    #pragma unroll
    for (int r = 0; r < 32; r++)
        Ws[t + r*256] = fc2w[t + r*256];
    __syncthreads();
    {   // phase B: emb = leaky(h@fc2+b2)
        const int db = sub * 4;
        float a0=0.f,a1=0.f,a2=0.f,a3=0.f;
        #pragma unroll
        for (int k = 0; k < H1; k++) {
            float hv = Hs[node*132 + k];
            float4 w = *reinterpret_cast<const float4*>(&Ws[k*EMBD + db]);
            a0 += hv*w.x; a1 += hv*w.y; a2 += hv*w.z; a3 += hv*w.w;
        }
        float v0 = a0 + fc2b[db+0]; v0 = v0 > 0.f ? v0 : 0.01f*v0;
        float v1 = a1 + fc2b[db+1]; v1 = v1 > 0.f ? v1 : 0.01f*v1;
        float v2 = a2 + fc2b[db+2]; v2 = v2 > 0.f ? v2 : 0.01f*v2;
        float v3 = a3 + fc2b[db+3]; v3 = v3 > 0.f ? v3 : 0.01f*v3;

        Es[node*EMBD + db + 0] = v0;
        Es[node*EMBD + db + 1] = v1;
        Es[node*EMBD + db + 2] = v2;
        Es[node*EMBD + db + 3] = v3;

        const int g = nb + node;
        float4 v4 = make_float4(v0, v1, v2, v3);
        *reinterpret_cast<float4*>(&g_emb[g*EMBD + db]) = v4;
        *reinterpret_cast<float4*>(&out[EMB_OFF + g*EMBD + db]) = v4;
    }

    __syncthreads();
    #pragma unroll
    for (int r = 0; r < 16; r++)
        Ws[t + r*256] = e1w[t + r*256];
    __syncthreads();
    {   // phase C: A = emb @ e1_w[:64,:]
        const int hb = sub * 4;
        float a0=0.f,a1=0.f,a2=0.f,a3=0.f;
        #pragma unroll
        for (int k = 0; k < EMBD; k++) {
            float ev = Es[node*EMBD + k];
            float4 w = *reinterpret_cast<const float4*>(&Ws[k*HE + hb]);
            a0 += ev*w.x; a1 += ev*w.y; a2 += ev*w.z; a3 += ev*w.w;
        }
        const int g = nb + node;
        *reinterpret_cast<float4*>(&g_A[g*HE + hb]) = make_float4(a0, a1, a2, a3);
    }
}

// =====================================================================
// Stage 2: edge GEMM via mma.sync (HMMA bf16, compensated split).
// =====================================================================
// smem byte offsets
#define EHB   0          // Eh: 512 x 64 bf16, 128B rows, SW128   = 65536
#define ELB   65536      // El: same                               = 65536
#define UHB   131072     // Uh: 64 x 64 bf16                       = 8192
#define ULB   139264     // Ul                                     = 8192
#define WB    147456     // e1w fp32 (W1 4096 floats, W2 4096)     = 32768
#define EMBA  180224     // emb_i 16 x 64 f32                      = 4096
#define CCB   184320     // cc 16 x 64 f32                         = 4096
#define WDB   188416     // wd 64 f32                              = 256
#define SM2_TOTAL 188800

__device__ __forceinline__ u32 bfpack(float lo, float hi) {
    u32 r;
    asm("cvt.rn.satfinite.bf16x2.f32 %0, %1, %2;" : "=r"(r) : "f"(hi), "f"(lo));
    return r;
}
__device__ __forceinline__ float bf_lo_f(u32 p) { return __uint_as_float(p << 16); }
__device__ __forceinline__ float bf_hi_f(u32 p) { return __uint_as_float(p & 0xFFFF0000u); }

__device__ __forceinline__ void ldsm4(u32& r0, u32& r1, u32& r2, u32& r3, u32 addr) {
    asm volatile("ldmatrix.sync.aligned.m8n8.x4.shared.b16 {%0,%1,%2,%3}, [%4];"
        : "=r"(r0), "=r"(r1), "=r"(r2), "=r"(r3) : "r"(addr));
}
__device__ __forceinline__ void ldsm4t(u32& r0, u32& r1, u32& r2, u32& r3, u32 addr) {
    asm volatile("ldmatrix.sync.aligned.m8n8.x4.trans.shared.b16 {%0,%1,%2,%3}, [%4];"
        : "=r"(r0), "=r"(r1), "=r"(r2), "=r"(r3) : "r"(addr));
}
__device__ __forceinline__ void mma16816(float* d, const u32* a, const u32* b) {
    asm volatile(
        "mma.sync.aligned.m16n8k16.row.col.f32.bf16.bf16.f32 "
        "{%0,%1,%2,%3}, {%4,%5,%6,%7}, {%8,%9}, {%0,%1,%2,%3};"
        : "+f"(d[0]), "+f"(d[1]), "+f"(d[2]), "+f"(d[3])
        : "r"(a[0]), "r"(a[1]), "r"(a[2]), "r"(a[3]), "r"(b[0]), "r"(b[1]));
}

__device__ __forceinline__ void store_edge(float* __restrict__ out,
                                           int b, int i, int j, float d) {
    float ad  = fabsf(d);
    float ex  = __expf(-ad);
    float inv = 1.f / (1.f + ex);
    float pbig = inv, psml = ex * inv;
    float p1 = d >= 0.f ? pbig : psml;
    float p0 = d >= 0.f ? psml : pbig;
    out[b*NN*NN + i*NN + j] = p1;
    if (j != i) {
        int kidx = i*(NN-1) + (j < i ? j : j - 1);
        reinterpret_cast<float2*>(out + PRED_OFF)[b*NPAIR + kidx] = make_float2(p0, p1);
    }
}

__global__ __launch_bounds__(256, 1)
void stage2m(const float* __restrict__ e1w, const float* __restrict__ e1b,
             const float* __restrict__ e2w, const float* __restrict__ e2b,
             float* __restrict__ out)
{
    extern __shared__ char smc[];
    const u32 sb = (u32)__cvta_generic_to_shared(smc);

    const int t    = threadIdx.x;
    const int lane = t & 31;
    const int wid  = t >> 5;
    const int b     = blockIdx.x >> 5;
    const int ibase = (blockIdx.x & 31) * 16;

    float* Wsm  = reinterpret_cast<float*>(smc + WB);
    float* embA = reinterpret_cast<float*>(smc + EMBA);
    float* ccs  = reinterpret_cast<float*>(smc + CCB);
    float* wds  = reinterpret_cast<float*>(smc + WDB);

    // ---- prologue: weights, emb_i, cc, wd ----
    #pragma unroll
    for (int r = 0; r < 8; r++)
        reinterpret_cast<float4*>(Wsm)[t + r*256] =
            reinterpret_cast<const float4*>(e1w)[t + r*256];
    reinterpret_cast<float4*>(embA)[t] =
        reinterpret_cast<const float4*>(&g_emb[(b*NN + ibase)*EMBD])[t];
    #pragma unroll
    for (int r = 0; r < 4; r++) {
        int idx = t + r*256, ii = idx >> 6, h = idx & 63;
        ccs[idx] = g_A[(b*NN + ibase + ii)*HE + h] + e1b[h];
    }
    if (t < 64) wds[t] = e2w[t*2 + 1] - e2w[t*2];
    const float bd = e2b[1] - e2b[0];

    // ---- E conversion: rows t, t+256 -> Eh/El (SW128 swizzled) ----
    #pragma unroll
    for (int rr = 0; rr < 2; rr++) {
        const int r = t + rr*256;
        const float4* src = reinterpret_cast<const float4*>(&g_emb[(b*NN + r)*EMBD]);
        char* ehrow = smc + EHB + r*128;
        char* elrow = smc + ELB + r*128;
        const int r7 = r & 7;
        #pragma unroll
        for (int c = 0; c < 8; c++) {
            float4 v0 = src[c*2], v1 = src[c*2 + 1];
            u32 h0 = bfpack(v0.x, v0.y), h1 = bfpack(v0.z, v0.w);
            u32 h2 = bfpack(v1.x, v1.y), h3 = bfpack(v1.z, v1.w);
            u32 l0 = bfpack(v0.x - bf_lo_f(h0), v0.y - bf_hi_f(h0));
            u32 l1 = bfpack(v0.z - bf_lo_f(h1), v0.w - bf_hi_f(h1));
            u32 l2 = bfpack(v1.x - bf_lo_f(h2), v1.y - bf_hi_f(h2));
            u32 l3 = bfpack(v1.z - bf_lo_f(h3), v1.w - bf_hi_f(h3));
            *reinterpret_cast<uint4*>(ehrow + ((c ^ r7) << 4)) = make_uint4(h0, h1, h2, h3);
            *reinterpret_cast<uint4*>(elrow + ((c ^ r7) << 4)) = make_uint4(l0, l1, l2, l3);
        }
    }
    __syncthreads();

    // wd into registers: thread's h-cols are ht*8 + 2*(lane&3) + {0,1}
    float wdr[16];
    {
        const int t2 = (lane & 3) * 2;
        #pragma unroll
        for (int ht = 0; ht < 8; ht++) {
            wdr[ht*2]     = wds[ht*8 + t2];
            wdr[ht*2 + 1] = wds[ht*8 + t2 + 1];
        }
    }

    const u32 EhA = sb + EHB, ElA = sb + ELB, UhA = sb + UHB, UlA = sb + ULB;
    const int wj   = wid * 64;
    const int lrow = lane & 15;
    const int lch  = lane >> 4;      // 0/1: k- or n- 8-chunk selector

    // ---- loop over 16 source nodes ----
    for (int ii = 0; ii < 16; ii++) {
        // build Uh/Ul for this i (all 256 threads; k = t>>2, 2 chunks each)
        {
            const int k  = t >> 2;
            const int c2 = (t & 3) * 2;
            const float e = embA[ii*64 + k];
            const float4* w1 = reinterpret_cast<const float4*>(&Wsm[k*64 + c2*8]);
            const float4* w2 = reinterpret_cast<const float4*>(&Wsm[4096 + k*64 + c2*8]);
            char* uh = smc + UHB + k*128;
            char* ul = smc + ULB + k*128;
            const int k7 = k & 7;
            #pragma unroll
            for (int q = 0; q < 2; q++) {
                float4 a0 = w1[q*2], a1 = w1[q*2 + 1];
                float4 b0 = w2[q*2], b1 = w2[q*2 + 1];
                float u0 = fmaf(e, b0.x, -a0.x), u1 = fmaf(e, b0.y, -a0.y);
                float u2 = fmaf(e, b0.z, -a0.z), u3 = fmaf(e, b0.w, -a0.w);
                float u4 = fmaf(e, b1.x, -a1.x), u5 = fmaf(e, b1.y, -a1.y);
                float u6 = fmaf(e, b1.z, -a1.z), u7 = fmaf(e, b1.w, -a1.w);
                u32 p0 = bfpack(u0, u1), p1 = bfpack(u2, u3);
                u32 p2 = bfpack(u4, u5), p3 = bfpack(u6, u7);
                u32 q0 = bfpack(u0 - bf_lo_f(p0), u1 - bf_hi_f(p0));
                u32 q1 = bfpack(u2 - bf_lo_f(p1), u3 - bf_hi_f(p1));
                u32 q2 = bfpack(u4 - bf_lo_f(p2), u5 - bf_hi_f(p2));
                u32 q3 = bfpack(u6 - bf_lo_f(p3), u7 - bf_hi_f(p3));
                const u32 co = (u32)(((c2 + q) ^ k7) << 4);
                *reinterpret_cast<uint4*>(uh + co) = make_uint4(p0, p1, p2, p3);
                *reinterpret_cast<uint4*>(ul + co) = make_uint4(q0, q1, q2, q3);
            }
        }
        __syncthreads();

        // mma: warp tile 64j x 64h, 3 compensation passes
        float acc[32][4];
        #pragma unroll
        for (int a = 0; a < 32; a++)
            #pragma unroll
            for (int c = 0; c < 4; c++) acc[a][c] = 0.f;

        #pragma unroll
        for (int p = 0; p < 3; p++) {
            const u32 Eb = (p == 2) ? ElA : EhA;
            const u32 Ub = (p == 1) ? UlA : UhA;
            #pragma unroll
            for (int ks = 0; ks < 4; ks++) {
                const int k0 = ks * 16;
                // B frags: 4 x ldmatrix.x4.trans covering k0..k0+15 x 64h
                u32 bfr[8][2];
                const int  kr  = k0 + lrow;
                const u32  brb = Ub + (u32)(kr * 128);
                const int  br7 = kr & 7;
                #pragma unroll
                for (int nb = 0; nb < 4; nb++) {
                    const u32 addr = brb + (u32)((((nb*2 + lch) ^ br7)) << 4);
                    ldsm4t(bfr[nb*2][0], bfr[nb*2][1],
                           bfr[nb*2+1][0], bfr[nb*2+1][1], addr);
                }
                #pragma unroll
                for (int jf = 0; jf < 4; jf++) {
                    const int ra = wj + jf*16 + lrow;
                    const u32 addr = Eb + (u32)(ra*128)
                                   + (u32)((((ks*2 + lch) ^ (ra & 7))) << 4);
                    u32 a[4];
                    ldsm4(a[0], a[1], a[2], a[3], addr);
                    #pragma unroll
                    for (int ht = 0; ht < 8; ht++)
                        mma16816(acc[jf*8 + ht], a, bfr[ht]);
                }
            }
        }

        // epilogue: relu + wd dot, bfly-reduce over lane%4, sigmoid, store
        {
            float ccr[16];
            const int t2 = (lane & 3) * 2;
            #pragma unroll
            for (int ht = 0; ht < 8; ht++) {
                ccr[ht*2]     = ccs[ii*64 + ht*8 + t2];
                ccr[ht*2 + 1] = ccs[ii*64 + ht*8 + t2 + 1];
            }
            const int ig2 = ibase + ii;
            #pragma unroll
            for (int jf = 0; jf < 4; jf++) {
                float s0 = 0.f, s1 = 0.f;
                #pragma unroll
                for (int ht = 0; ht < 8; ht++) {
                    s0 += fmaxf(acc[jf*8+ht][0] + ccr[ht*2],     0.f) * wdr[ht*2]
                        + fmaxf(acc[jf*8+ht][1] + ccr[ht*2 + 1], 0.f) * wdr[ht*2 + 1];
                    s1 += fmaxf(acc[jf*8+ht][2] + ccr[ht*2],     0.f) * wdr[ht*2]
                        + fmaxf(acc[jf*8+ht][3] + ccr[ht*2 + 1], 0.f) * wdr[ht*2 + 1];
                }
                s0 += __shfl_xor_sync(0xffffffffu, s0, 1);
                s0 += __shfl_xor_sync(0xffffffffu, s0, 2);
                s1 += __shfl_xor_sync(0xffffffffu, s1, 1);
                s1 += __shfl_xor_sync(0xffffffffu, s1, 2);
                if ((lane & 3) == 0) {
                    const int j0 = wj + jf*16 + (lane >> 2);
                    store_edge(out, b, ig2, j0,     s0 + bd);
                    store_edge(out, b, ig2, j0 + 8, s1 + bd);
                }
            }
        }
        __syncthreads();
    }
}

// =====================================================================
extern "C" void kernel_launch(void* const* d_in, const int* in_sizes, int n_in,
                              void* d_out, int out_size)
{
    (void)in_sizes; (void)n_in; (void)out_size;
    const float* nf   = (const float*)d_in[0];
    const float* fc1w = (const float*)d_in[1];
    const float* fc1b = (const float*)d_in[2];
    const float* fc2w = (const float*)d_in[3];
    const float* fc2b = (const float*)d_in[4];
    const float* e1w  = (const float*)d_in[5];
    const float* e1b  = (const float*)d_in[6];
    const float* e2w  = (const float*)d_in[7];
    const float* e2b  = (const float*)d_in[8];
    float* out = (float*)d_out;

    const int smem1 = 15424 * 4;
    cudaFuncSetAttribute(stage1, cudaFuncAttributeMaxDynamicSharedMemorySize, smem1);
    cudaFuncSetAttribute(stage2m, cudaFuncAttributeMaxDynamicSharedMemorySize, SM2_TOTAL);

    stage1<<<128, 256, smem1>>>(nf, fc1w, fc1b, fc2w, fc2b, e1w, out);
    stage2m<<<128, 256, SM2_TOTAL>>>(e1w, e1b, e2w, e2b, out);
}